// round 15
// baseline (speedup 1.0000x reference)
#include <cuda_runtime.h>
#include <cmath>

// Problem constants
#define TT   50
#define PAD  49
#define EXT  148              // PAD + TT + PAD
#define BB   50
#define CC   4096
#define BC   (BB * CC)        // 204800 channels
#define NBAND 2
#define CTILE 8               // channels (c) per block
#define BLKT (BB * CTILE)     // 400 threads: thread (b, c_local)

// ================= compile-time Butterworth bandpass design =================
// Mirrors the reference numpy code exactly, evaluated in double at compile time.

__host__ __device__ constexpr double c_sin(double x) {
    double t = x, s = x;
    for (int k = 1; k <= 15; k++) { t *= -x * x / ((2.0 * k) * (2.0 * k + 1.0)); s += t; }
    return s;
}
__host__ __device__ constexpr double c_cos(double x) {
    double t = 1.0, s = 1.0;
    for (int k = 1; k <= 15; k++) { t *= -x * x / ((2.0 * k - 1.0) * (2.0 * k)); s += t; }
    return s;
}
__host__ __device__ constexpr double c_tan(double x) { return c_sin(x) / c_cos(x); }
__host__ __device__ constexpr double c_sqrt(double x) {
    if (x <= 0.0) return 0.0;
    double y = x > 1.0 ? x : 1.0;
    for (int i = 0; i < 100; i++) y = 0.5 * (y + x / y);
    return y;
}

struct CD { double re, im; };
__host__ __device__ constexpr CD cmul(CD a, CD b) { return {a.re * b.re - a.im * b.im, a.re * b.im + a.im * b.re}; }
__host__ __device__ constexpr CD cdiv(CD a, CD b) {
    double d = b.re * b.re + b.im * b.im;
    return {(a.re * b.re + a.im * b.im) / d, (a.im * b.re - a.re * b.im) / d};
}
__host__ __device__ constexpr CD csqrt(CD z) {
    double r = c_sqrt(z.re * z.re + z.im * z.im);
    double re = c_sqrt((r + z.re) * 0.5);
    double im = c_sqrt((r - z.re) * 0.5);
    return {re, z.im >= 0.0 ? im : -im};
}

struct BandCoef {
    double b0_0, b2_0, a1_0, a2_0, zi0_0, zi1_0;   // section 0
    double b0_1, b2_1, a1_1, a2_1, zi0_1, zi1_1;   // section 1
};

__host__ __device__ constexpr BandCoef design(double w1, double w2) {
    const double PI = 3.14159265358979323846264338327950288;
    const double RT2_2 = 0.70710678118654752440;   // sqrt(2)/2
    const double W1 = 4.0 * c_tan(PI * w1 / 2.0);
    const double W2 = 4.0 * c_tan(PI * w2 / 2.0);
    const double bw = W2 - W1;
    const double wo = c_sqrt(W1 * W2);

    CD p[2] = { {-RT2_2, -RT2_2}, {RT2_2, -RT2_2} };
    CD pbp[4] = { {0,0},{0,0},{0,0},{0,0} };
    for (int k = 0; k < 2; k++) {
        CD plp = {p[k].re * bw * 0.5, p[k].im * bw * 0.5};
        CD disc = csqrt({plp.re * plp.re - plp.im * plp.im - wo * wo,
                         2.0 * plp.re * plp.im});
        pbp[k]     = {plp.re + disc.re, plp.im + disc.im};
        pbp[k + 2] = {plp.re - disc.re, plp.im - disc.im};
    }
    const double fs2 = 4.0;
    CD prod = {1.0, 0.0};
    for (int i = 0; i < 4; i++) prod = cmul(prod, {fs2 - pbp[i].re, -pbp[i].im});
    const double gain = bw * bw * fs2 * fs2 / prod.re;

    CD pos[2] = { {0,0},{0,0} };
    int np = 0;
    for (int i = 0; i < 4; i++) {
        CD pd = cdiv({fs2 + pbp[i].re, pbp[i].im}, {fs2 - pbp[i].re, -pbp[i].im});
        if (pd.im > 0.0 && np < 2) { pos[np] = pd; np++; }
    }

    BandCoef bc = {};
    bc.b0_0 = gain;  bc.b2_0 = -gain;
    bc.a1_0 = -2.0 * pos[0].re;  bc.a2_0 = pos[0].re * pos[0].re + pos[0].im * pos[0].im;
    bc.b0_1 = 1.0;   bc.b2_1 = -1.0;
    bc.a1_1 = -2.0 * pos[1].re;  bc.a2_1 = pos[1].re * pos[1].re + pos[1].im * pos[1].im;

    double scale = 1.0;
    {
        const double b0 = bc.b0_0, b2 = bc.b2_0, a1 = bc.a1_0, a2 = bc.a2_0;
        const double B0 = -a1 * b0;
        const double B1 = b2 - a2 * b0;
        const double det = 1.0 + a1 + a2;
        bc.zi0_0 = scale * (B0 + B1) / det;
        bc.zi1_0 = scale * ((1.0 + a1) * B1 - a2 * B0) / det;
        scale *= (b0 + b2) / (1.0 + a1 + a2);
    }
    {
        const double b0 = bc.b0_1, b2 = bc.b2_1, a1 = bc.a1_1, a2 = bc.a2_1;
        const double B0 = -a1 * b0;
        const double B1 = b2 - a2 * b0;
        const double det = 1.0 + a1 + a2;
        bc.zi0_1 = scale * (B0 + B1) / det;
        bc.zi1_1 = scale * ((1.0 + a1) * B1 - a2 * B0) / det;
    }
    return bc;
}

// ===== compile-time W: demeaned filtfilt as a 50x50 linear map (impulse responses) =====
struct Wmat { float w[TT][TT]; };

__host__ __device__ constexpr Wmat make_W(int band) {
    const BandCoef bc = (band == 0) ? design(0.05, 0.15) : design(0.2, 0.4);
    Wmat W = {};
    for (int k = 0; k < TT; k++) {
        double xs[TT] = {};
        xs[k] = 1.0;

        // odd extension (padlen = 49), exactly as reference _odd_ext
        double ext[EXT] = {};
        for (int i = 0; i < PAD; i++) ext[i] = 2.0 * xs[0] - xs[PAD - i];
        for (int t = 0; t < TT; t++) ext[PAD + t] = xs[t];
        for (int i = 0; i < PAD; i++) ext[PAD + TT + i] = 2.0 * xs[TT - 1] - xs[TT - 2 - i];

        // forward sosfilt (2 cascaded biquads, DF2T), zi scaled by ext[0]
        {
            const double e0 = ext[0];
            double z00 = bc.zi0_0 * e0, z01 = bc.zi1_0 * e0;
            double z10 = bc.zi0_1 * e0, z11 = bc.zi1_1 * e0;
            for (int i = 0; i < EXT; i++) {
                const double xt = ext[i];
                const double y0 = bc.b0_0 * xt + z00;
                z00 = z01 - bc.a1_0 * y0;
                z01 = bc.b2_0 * xt - bc.a2_0 * y0;
                const double y1 = bc.b0_1 * y0 + z10;
                z10 = z11 - bc.a1_1 * y1;
                z11 = bc.b2_1 * y0 - bc.a2_1 * y1;
                ext[i] = y1;
            }
        }
        // backward sosfilt on reversed signal, zi scaled by ext[EXT-1]
        {
            const double el = ext[EXT - 1];
            double z00 = bc.zi0_0 * el, z01 = bc.zi1_0 * el;
            double z10 = bc.zi0_1 * el, z11 = bc.zi1_1 * el;
            for (int i = EXT - 1; i >= 0; i--) {
                const double xt = ext[i];
                const double y0 = bc.b0_0 * xt + z00;
                z00 = z01 - bc.a1_0 * y0;
                z01 = bc.b2_0 * xt - bc.a2_0 * y0;
                const double y1 = bc.b0_1 * y0 + z10;
                z10 = z11 - bc.a1_1 * y1;
                z11 = bc.b2_1 * y0 - bc.a2_1 * y1;
                ext[i] = y1;
            }
        }
        // central crop + demean over T (both linear -> folded into W)
        double mean = 0.0;
        for (int t = 0; t < TT; t++) mean += ext[PAD + t];
        mean /= (double)TT;
        for (int t = 0; t < TT; t++)
            W.w[t][k] = (float)(ext[PAD + t] - mean);
    }
    return W;
}

// ================================ kernels ================================

template <int BAND>
__global__ void __launch_bounds__(BLKT, 2)
gemm_fused_kernel(const float* __restrict__ x, float* __restrict__ out) {
    // function-local constexpr: compile-time values, usable in device code,
    // folds into FFMA immediate operands
    constexpr Wmat W = make_W(BAND);

    __shared__ float s_m2 [TT][CTILE];
    __shared__ float s_inv[TT][CTILE];

    const int tid = threadIdx.x;           // < 400
    const int b   = tid >> 3;              // 0..49 (stat provider for t = b)
    const int cl  = tid & (CTILE - 1);     // 0..7
    const int c   = blockIdx.x * CTILE + cl;
    const int ch  = b * CC + c;            // channel in [0, BC)
    const float* xc = x + ch;

    // yd = W x : 50 independent accumulator chains (full ILP, all-imm FFMA)
    float acc[TT] = {};
    #pragma unroll
    for (int k = 0; k < TT; k++) {
        const float xk = xc[(size_t)k * BC];
        #pragma unroll
        for (int t = 0; t < TT; t++)
            acc[t] = fmaf(W.w[t][k], xk, acc[t]);
    }

    // z-score stats of this channel (ddof=1)
    float s = 0.0f;
    #pragma unroll
    for (int t = 0; t < TT; t++) s += acc[t];
    const float m2 = s * (1.0f / TT);

    float v = 0.0f;
    #pragma unroll
    for (int t = 0; t < TT; t++) {
        const float d = acc[t] - m2;
        v = fmaf(d, d, v);
    }

    s_m2[b][cl]  = m2;
    s_inv[b][cl] = rsqrtf(v * (1.0f / (TT - 1)));
    __syncthreads();

    // normalize with stats of channel (b'=t, c) — the reference's broadcast quirk (T==B)
    float* ob = out + (size_t)BAND * TT * BC + ch;
    #pragma unroll
    for (int t = 0; t < TT; t++)
        ob[(size_t)t * BC] = (acc[t] - s_m2[t][cl]) * s_inv[t][cl];
}

extern "C" void kernel_launch(void* const* d_in, const int* in_sizes, int n_in,
                              void* d_out, int out_size) {
    const float* x = (const float*)d_in[0];
    float* out = (float*)d_out;

    gemm_fused_kernel<0><<<CC / CTILE, BLKT>>>(x, out);   // 512 blocks
    gemm_fused_kernel<1><<<CC / CTILE, BLKT>>>(x, out);   // x re-read hits L2
}